// round 3
// baseline (speedup 1.0000x reference)
#include <cuda_runtime.h>

#define B_ 4
#define D_ 8
#define F_ 256
#define C_ 512
#define R_ 64
#define NPOS (B_*D_*F_)   /* 8192 */
#define NB (D_*F_)        /* 2048 keys per batch */

// Scratch (static device allocations are allowed; runtime allocs are not)
__device__ float g_Q[NPOS * R_];    // 2 MB
__device__ float g_K[NPOS * R_];    // 2 MB
__device__ float g_V[NPOS * C_];    // 16 MB
__device__ float g_Wt[NPOS * F_];   // 8 MB  (unnormalized attn weights, g-folded)
__device__ float g_Y1[NPOS * C_];   // 16 MB

// ---------------------------------------------------------------------------
// Generic GEMM: C[M,N] = A[M,K] @ W[K,N] + bias[N]
// 64x64 block tile, 256 threads, 4x4 per-thread microtile, K-chunks of 16.
// ---------------------------------------------------------------------------
__global__ __launch_bounds__(256) void gemm_bias_kernel(
    const float* __restrict__ A, const float* __restrict__ W,
    const float* __restrict__ bias, float* __restrict__ Cout,
    int M, int N, int K)
{
    __shared__ float As[16][68];   // [k][m], padded (68*4B = 17*16B keeps 16B align)
    __shared__ float Bs[16][64];   // [k][n]

    const int tid = threadIdx.x;
    const int tx = tid & 15, ty = tid >> 4;
    const int m0 = blockIdx.x * 64;
    const int n0 = blockIdx.y * 64;

    const int la_m = tid >> 2;
    const int la_k = (tid & 3) << 2;
    const int lb_k = tid >> 4;
    const int lb_n = (tid & 15) << 2;

    float acc[4][4] = {};

    for (int k0 = 0; k0 < K; k0 += 16) {
        float4 av = *(const float4*)&A[(m0 + la_m) * K + (k0 + la_k)];
        float4 bv = *(const float4*)&W[(k0 + lb_k) * N + (n0 + lb_n)];
        __syncthreads();
        As[la_k + 0][la_m] = av.x;
        As[la_k + 1][la_m] = av.y;
        As[la_k + 2][la_m] = av.z;
        As[la_k + 3][la_m] = av.w;
        *(float4*)&Bs[lb_k][lb_n] = bv;
        __syncthreads();
#pragma unroll
        for (int kk = 0; kk < 16; kk++) {
            float4 a4 = *(const float4*)&As[kk][ty << 2];
            float4 b4 = *(const float4*)&Bs[kk][tx << 2];
            float ar[4] = {a4.x, a4.y, a4.z, a4.w};
            float br[4] = {b4.x, b4.y, b4.z, b4.w};
#pragma unroll
            for (int i = 0; i < 4; i++)
#pragma unroll
                for (int j = 0; j < 4; j++)
                    acc[i][j] += ar[i] * br[j];
        }
    }

    float4 bb = *(const float4*)&bias[n0 + (tx << 2)];
    float bbr[4] = {bb.x, bb.y, bb.z, bb.w};
#pragma unroll
    for (int i = 0; i < 4; i++) {
        int row = m0 + (ty << 2) + i;
        float4 o;
        o.x = acc[i][0] + bbr[0];
        o.y = acc[i][1] + bbr[1];
        o.z = acc[i][2] + bbr[2];
        o.w = acc[i][3] + bbr[3];
        *(float4*)&Cout[row * N + n0 + (tx << 2)] = o;
    }
}

// ---------------------------------------------------------------------------
// Scores + softmax-numerator fold over key depth g.
// Block: 32 queries (fixed batch) x 128 key-f columns; loops g=0..7, keeping
// w[h] = sum_g exp(q . K[g,h]) in registers. Writes unnormalized weights.
// Softmax is shift-invariant and |e| <~ 9 here, so no max subtraction needed.
// Grid: (F_/128=2, NB/32=64, B_=4), 256 threads.
// ---------------------------------------------------------------------------
__global__ __launch_bounds__(256) void scores_kernel(
    const float* __restrict__ Q, const float* __restrict__ K,
    float* __restrict__ Wt)
{
    __shared__ float Qs[32][64];    // [q][r]
    __shared__ float Ks[128][65];   // [k][r], +1 pad to spread banks

    const int tid = threadIdx.x;
    const int b = blockIdx.z;
    const int q0 = blockIdx.y * 32;
    const int h0 = blockIdx.x * 128;
    const int tx = tid & 31, ty = tid >> 5;

#pragma unroll
    for (int it = 0; it < 2; it++) {
        int idx4 = tid + it * 256;
        int q = idx4 >> 4, r = (idx4 & 15) << 2;
        *(float4*)&Qs[q][r] = *(const float4*)&Q[(b * NB + q0 + q) * R_ + r];
    }

    float wacc[4][4] = {};

    for (int g = 0; g < 8; g++) {
        __syncthreads();   // first iter: publishes Qs; later: guards Ks reuse
#pragma unroll
        for (int it = 0; it < 8; it++) {
            int idx4 = tid + it * 256;
            int k = idx4 >> 4, r = (idx4 & 15) << 2;
            float4 v = *(const float4*)&K[(b * NB + g * F_ + h0 + k) * R_ + r];
            Ks[k][r + 0] = v.x;
            Ks[k][r + 1] = v.y;
            Ks[k][r + 2] = v.z;
            Ks[k][r + 3] = v.w;
        }
        __syncthreads();

        float acc[4][4] = {};
#pragma unroll 4
        for (int r = 0; r < 64; r++) {
            float a[4], bb[4];
#pragma unroll
            for (int j = 0; j < 4; j++) a[j] = Qs[(ty << 2) + j][r];
#pragma unroll
            for (int j = 0; j < 4; j++) bb[j] = Ks[(tx << 2) + j][r];
#pragma unroll
            for (int i = 0; i < 4; i++)
#pragma unroll
                for (int j = 0; j < 4; j++)
                    acc[i][j] += a[i] * bb[j];
        }
#pragma unroll
        for (int i = 0; i < 4; i++)
#pragma unroll
            for (int j = 0; j < 4; j++)
                wacc[i][j] += __expf(acc[i][j]);
    }

#pragma unroll
    for (int i = 0; i < 4; i++) {
        int row = b * NB + q0 + (ty << 2) + i;
        float4 o = {wacc[i][0], wacc[i][1], wacc[i][2], wacc[i][3]};
        *(float4*)&Wt[row * F_ + h0 + (tx << 2)] = o;
    }
}

// ---------------------------------------------------------------------------
// attn = (w/Z) @ V[b,d]; fused with residual + LayerNorm -> Y1.
// Block: 16 rows x full 512 cols (so LN is block-local). 256 threads,
// per-thread 2 rows x 16 cols (4 column groups of 4, interleaved by 128).
// Row scaling by 1/Z commuted to the epilogue.
// ---------------------------------------------------------------------------
__global__ __launch_bounds__(256) void attn_ln_kernel(
    const float* __restrict__ Wt, const float* __restrict__ V,
    const float* __restrict__ x, const float* __restrict__ g1,
    const float* __restrict__ b1, float* __restrict__ Y1)
{
    __shared__ float Bs[16][512];  // V k-tile; reused as t-value stash
    __shared__ float As[16][16];   // w tile [r][k]

    const int tid = threadIdx.x;
    const int row0 = blockIdx.x * 16;
    const int vbase = row0 & ~(F_ - 1);   // all 16 rows share (b,d)
    const int tx = tid & 31, ty = tid >> 5;
    const int ar = tid >> 4, ak = tid & 15;

    float acc[2][16] = {};

    for (int k0 = 0; k0 < F_; k0 += 16) {
        float a_v = Wt[(row0 + ar) * F_ + (k0 + ak)];
        float4 bv[8];
#pragma unroll
        for (int it = 0; it < 8; it++) {
            int idx4 = tid + it * 256;
            int k = idx4 >> 7, c = (idx4 & 127) << 2;
            bv[it] = *(const float4*)&V[(vbase + k0 + k) * C_ + c];
        }
        __syncthreads();
        As[ar][ak] = a_v;
#pragma unroll
        for (int it = 0; it < 8; it++) {
            int idx4 = tid + it * 256;
            int k = idx4 >> 7, c = (idx4 & 127) << 2;
            *(float4*)&Bs[k][c] = bv[it];
        }
        __syncthreads();
#pragma unroll
        for (int kk = 0; kk < 16; kk++) {
            float a0 = As[(ty << 1) + 0][kk];
            float a1 = As[(ty << 1) + 1][kk];
#pragma unroll
            for (int cg = 0; cg < 4; cg++) {
                float4 b4 = *(const float4*)&Bs[kk][cg * 128 + (tx << 2)];
                float br[4] = {b4.x, b4.y, b4.z, b4.w};
#pragma unroll
                for (int j = 0; j < 4; j++) {
                    acc[0][cg * 4 + j] += a0 * br[j];
                    acc[1][cg * 4 + j] += a1 * br[j];
                }
            }
        }
    }

    __syncthreads();
#pragma unroll
    for (int r = 0; r < 2; r++)
#pragma unroll
        for (int cg = 0; cg < 4; cg++) {
            float4 o = {acc[r][cg*4+0], acc[r][cg*4+1], acc[r][cg*4+2], acc[r][cg*4+3]};
            *(float4*)&Bs[(ty << 1) + r][cg * 128 + (tx << 2)] = o;
        }
    __syncthreads();

    const int lane = tid & 31, wp = tid >> 5;
#pragma unroll
    for (int rr = 0; rr < 2; rr++) {
        int r = (wp << 1) + rr;
        int grow = row0 + r;
        float z = 0.f;
#pragma unroll
        for (int j = 0; j < 8; j++) z += Wt[grow * F_ + j * 32 + lane];
#pragma unroll
        for (int off = 16; off; off >>= 1) z += __shfl_xor_sync(0xffffffffu, z, off);
        float invz = 1.0f / z;

        float vals[16], s1 = 0.f, s2 = 0.f;
#pragma unroll
        for (int j = 0; j < 16; j++) {
            int c = j * 32 + lane;
            float v = Bs[r][c] * invz + x[grow * C_ + c];
            vals[j] = v; s1 += v; s2 += v * v;
        }
#pragma unroll
        for (int off = 16; off; off >>= 1) {
            s1 += __shfl_xor_sync(0xffffffffu, s1, off);
            s2 += __shfl_xor_sync(0xffffffffu, s2, off);
        }
        float mean = s1 * (1.f / 512.f);
        float var = s2 * (1.f / 512.f) - mean * mean;
        float rstd = rsqrtf(var + 1e-3f);
#pragma unroll
        for (int j = 0; j < 16; j++) {
            int c = j * 32 + lane;
            Y1[grow * C_ + c] = (vals[j] - mean) * rstd * g1[c] + b1[c];
        }
    }
}

// ---------------------------------------------------------------------------
// y2 = LN(y1 + relu(y1 @ wm + bm)) -> final output. Same structure as above.
// ---------------------------------------------------------------------------
__global__ __launch_bounds__(256) void mlp_ln_kernel(
    const float* __restrict__ Y1, const float* __restrict__ Wm,
    const float* __restrict__ bm, const float* __restrict__ g2,
    const float* __restrict__ b2, float* __restrict__ Out)
{
    __shared__ float Bs[16][512];
    __shared__ float As[16][16];

    const int tid = threadIdx.x;
    const int row0 = blockIdx.x * 16;
    const int tx = tid & 31, ty = tid >> 5;
    const int ar = tid >> 4, ak = tid & 15;

    float acc[2][16] = {};

    for (int k0 = 0; k0 < C_; k0 += 16) {
        float a_v = Y1[(row0 + ar) * C_ + (k0 + ak)];
        float4 bv[8];
#pragma unroll
        for (int it = 0; it < 8; it++) {
            int idx4 = tid + it * 256;
            int k = idx4 >> 7, c = (idx4 & 127) << 2;
            bv[it] = *(const float4*)&Wm[(k0 + k) * C_ + c];
        }
        __syncthreads();
        As[ar][ak] = a_v;
#pragma unroll
        for (int it = 0; it < 8; it++) {
            int idx4 = tid + it * 256;
            int k = idx4 >> 7, c = (idx4 & 127) << 2;
            *(float4*)&Bs[k][c] = bv[it];
        }
        __syncthreads();
#pragma unroll
        for (int kk = 0; kk < 16; kk++) {
            float a0 = As[(ty << 1) + 0][kk];
            float a1 = As[(ty << 1) + 1][kk];
#pragma unroll
            for (int cg = 0; cg < 4; cg++) {
                float4 b4 = *(const float4*)&Bs[kk][cg * 128 + (tx << 2)];
                float br[4] = {b4.x, b4.y, b4.z, b4.w};
#pragma unroll
                for (int j = 0; j < 4; j++) {
                    acc[0][cg * 4 + j] += a0 * br[j];
                    acc[1][cg * 4 + j] += a1 * br[j];
                }
            }
        }
    }

    __syncthreads();
#pragma unroll
    for (int r = 0; r < 2; r++)
#pragma unroll
        for (int cg = 0; cg < 4; cg++) {
            float4 o = {acc[r][cg*4+0], acc[r][cg*4+1], acc[r][cg*4+2], acc[r][cg*4+3]};
            *(float4*)&Bs[(ty << 1) + r][cg * 128 + (tx << 2)] = o;
        }
    __syncthreads();

    const int lane = tid & 31, wp = tid >> 5;
#pragma unroll
    for (int rr = 0; rr < 2; rr++) {
        int r = (wp << 1) + rr;
        int grow = row0 + r;

        float vals[16], s1 = 0.f, s2 = 0.f;
#pragma unroll
        for (int j = 0; j < 16; j++) {
            int c = j * 32 + lane;
            float mlp = fmaxf(Bs[r][c] + bm[c], 0.f);
            float v = Y1[grow * C_ + c] + mlp;
            vals[j] = v; s1 += v; s2 += v * v;
        }
#pragma unroll
        for (int off = 16; off; off >>= 1) {
            s1 += __shfl_xor_sync(0xffffffffu, s1, off);
            s2 += __shfl_xor_sync(0xffffffffu, s2, off);
        }
        float mean = s1 * (1.f / 512.f);
        float var = s2 * (1.f / 512.f) - mean * mean;
        float rstd = rsqrtf(var + 1e-3f);
#pragma unroll
        for (int j = 0; j < 16; j++) {
            int c = j * 32 + lane;
            Out[grow * C_ + c] = (vals[j] - mean) * rstd * g2[c] + b2[c];
        }
    }
}

// ---------------------------------------------------------------------------
extern "C" void kernel_launch(void* const* d_in, const int* in_sizes, int n_in,
                              void* d_out, int out_size)
{
    const float* x  = (const float*)d_in[0];
    const float* wq = (const float*)d_in[1];
    const float* bq = (const float*)d_in[2];
    const float* wk = (const float*)d_in[3];
    const float* bk = (const float*)d_in[4];
    const float* wv = (const float*)d_in[5];
    const float* bv = (const float*)d_in[6];
    const float* wm = (const float*)d_in[7];
    const float* bm = (const float*)d_in[8];
    const float* g1 = (const float*)d_in[9];
    const float* b1 = (const float*)d_in[10];
    const float* g2 = (const float*)d_in[11];
    const float* b2 = (const float*)d_in[12];
    float* out = (float*)d_out;

    float *Qp, *Kp, *Vp, *Wp, *Y1p;
    cudaGetSymbolAddress((void**)&Qp,  g_Q);
    cudaGetSymbolAddress((void**)&Kp,  g_K);
    cudaGetSymbolAddress((void**)&Vp,  g_V);
    cudaGetSymbolAddress((void**)&Wp,  g_Wt);
    cudaGetSymbolAddress((void**)&Y1p, g_Y1);

    // 1) Projections
    gemm_bias_kernel<<<dim3(NPOS / 64, 1), 256>>>(x, wq, bq, Qp, NPOS, R_, C_);
    gemm_bias_kernel<<<dim3(NPOS / 64, 1), 256>>>(x, wk, bk, Kp, NPOS, R_, C_);
    gemm_bias_kernel<<<dim3(NPOS / 64, C_ / 64), 256>>>(x, wv, bv, Vp, NPOS, C_, C_);

    // 2) Scores + g-fold (unnormalized softmax numerators)
    scores_kernel<<<dim3(F_ / 128, NB / 32, B_), 256>>>(Qp, Kp, Wp);

    // 3) attn + residual + LN
    attn_ln_kernel<<<NPOS / 16, 256>>>(Wp, Vp, x, g1, b1, Y1p);

    // 4) MLP + residual + LN -> out
    mlp_ln_kernel<<<NPOS / 16, 256>>>(Y1p, wm, bm, g2, b2, out);
}

// round 4
// speedup vs baseline: 1.0741x; 1.0741x over previous
#include <cuda_runtime.h>

#define B_ 4
#define D_ 8
#define F_ 256
#define C_ 512
#define R_ 64
#define NPOS (B_*D_*F_)   /* 8192 */
#define NB (D_*F_)        /* 2048 keys per batch */

// Scratch (static device allocations are allowed; runtime allocs are not)
__device__ float g_Q[NPOS * R_];    // 2 MB
__device__ float g_K[NPOS * R_];    // 2 MB
__device__ float g_V[NPOS * C_];    // 16 MB
__device__ float g_Wt[NPOS * F_];   // 8 MB  (unnormalized attn weights, g-folded)
__device__ float g_Y1[NPOS * C_];   // 16 MB

// ---------------------------------------------------------------------------
// Generic GEMM: C[M,N] = A[M,K] @ W[K,N] + bias[N]
// 64x64 block tile, 256 threads, 4x4 per-thread microtile, K-chunks of 16.
// ---------------------------------------------------------------------------
__global__ __launch_bounds__(256) void gemm_bias_kernel(
    const float* __restrict__ A, const float* __restrict__ W,
    const float* __restrict__ bias, float* __restrict__ Cout,
    int M, int N, int K)
{
    __shared__ float As[16][68];   // [k][m], padded (68*4B = 17*16B keeps 16B align)
    __shared__ float Bs[16][64];   // [k][n]

    const int tid = threadIdx.x;
    const int tx = tid & 15, ty = tid >> 4;
    const int m0 = blockIdx.x * 64;
    const int n0 = blockIdx.y * 64;

    const int la_m = tid >> 2;
    const int la_k = (tid & 3) << 2;
    const int lb_k = tid >> 4;
    const int lb_n = (tid & 15) << 2;

    float acc[4][4] = {};

    for (int k0 = 0; k0 < K; k0 += 16) {
        float4 av = *(const float4*)&A[(m0 + la_m) * K + (k0 + la_k)];
        float4 bv = *(const float4*)&W[(k0 + lb_k) * N + (n0 + lb_n)];
        __syncthreads();
        As[la_k + 0][la_m] = av.x;
        As[la_k + 1][la_m] = av.y;
        As[la_k + 2][la_m] = av.z;
        As[la_k + 3][la_m] = av.w;
        *(float4*)&Bs[lb_k][lb_n] = bv;
        __syncthreads();
#pragma unroll
        for (int kk = 0; kk < 16; kk++) {
            float4 a4 = *(const float4*)&As[kk][ty << 2];
            float4 b4 = *(const float4*)&Bs[kk][tx << 2];
            float ar[4] = {a4.x, a4.y, a4.z, a4.w};
            float br[4] = {b4.x, b4.y, b4.z, b4.w};
#pragma unroll
            for (int i = 0; i < 4; i++)
#pragma unroll
                for (int j = 0; j < 4; j++)
                    acc[i][j] += ar[i] * br[j];
        }
    }

    float4 bb = *(const float4*)&bias[n0 + (tx << 2)];
    float bbr[4] = {bb.x, bb.y, bb.z, bb.w};
#pragma unroll
    for (int i = 0; i < 4; i++) {
        int row = m0 + (ty << 2) + i;
        float4 o;
        o.x = acc[i][0] + bbr[0];
        o.y = acc[i][1] + bbr[1];
        o.z = acc[i][2] + bbr[2];
        o.w = acc[i][3] + bbr[3];
        *(float4*)&Cout[row * N + n0 + (tx << 2)] = o;
    }
}

// ---------------------------------------------------------------------------
// Scores + softmax-numerator fold over key depth g.
// Block: 32 queries (fixed batch) x 128 key-f columns; loops g=0..7, keeping
// w[h] = sum_g exp(q . K[g,h]) in registers. Writes unnormalized weights.
// Softmax is shift-invariant and |e| <~ 9 here, so no max subtraction needed.
// Grid: (F_/128=2, NB/32=64, B_=4), 256 threads.
// ---------------------------------------------------------------------------
__global__ __launch_bounds__(256) void scores_kernel(
    const float* __restrict__ Q, const float* __restrict__ K,
    float* __restrict__ Wt)
{
    __shared__ float Qs[32][64];    // [q][r]
    __shared__ float Ks[128][65];   // [k][r], +1 pad to spread banks

    const int tid = threadIdx.x;
    const int b = blockIdx.z;
    const int q0 = blockIdx.y * 32;
    const int h0 = blockIdx.x * 128;
    const int tx = tid & 31, ty = tid >> 5;

#pragma unroll
    for (int it = 0; it < 2; it++) {
        int idx4 = tid + it * 256;
        int q = idx4 >> 4, r = (idx4 & 15) << 2;
        *(float4*)&Qs[q][r] = *(const float4*)&Q[(b * NB + q0 + q) * R_ + r];
    }

    float wacc[4][4] = {};

    for (int g = 0; g < 8; g++) {
        __syncthreads();   // first iter: publishes Qs; later: guards Ks reuse
#pragma unroll
        for (int it = 0; it < 8; it++) {
            int idx4 = tid + it * 256;
            int k = idx4 >> 4, r = (idx4 & 15) << 2;
            float4 v = *(const float4*)&K[(b * NB + g * F_ + h0 + k) * R_ + r];
            Ks[k][r + 0] = v.x;
            Ks[k][r + 1] = v.y;
            Ks[k][r + 2] = v.z;
            Ks[k][r + 3] = v.w;
        }
        __syncthreads();

        float acc[4][4] = {};
#pragma unroll 4
        for (int r = 0; r < 64; r++) {
            float a[4], bb[4];
#pragma unroll
            for (int j = 0; j < 4; j++) a[j] = Qs[(ty << 2) + j][r];
#pragma unroll
            for (int j = 0; j < 4; j++) bb[j] = Ks[(tx << 2) + j][r];
#pragma unroll
            for (int i = 0; i < 4; i++)
#pragma unroll
                for (int j = 0; j < 4; j++)
                    acc[i][j] += a[i] * bb[j];
        }
#pragma unroll
        for (int i = 0; i < 4; i++)
#pragma unroll
            for (int j = 0; j < 4; j++)
                wacc[i][j] += __expf(acc[i][j]);
    }

#pragma unroll
    for (int i = 0; i < 4; i++) {
        int row = b * NB + q0 + (ty << 2) + i;
        float4 o = {wacc[i][0], wacc[i][1], wacc[i][2], wacc[i][3]};
        *(float4*)&Wt[row * F_ + h0 + (tx << 2)] = o;
    }
}

// ---------------------------------------------------------------------------
// attn = (w/Z) @ V[b,d]; fused with residual + LayerNorm -> Y1.
// Block: 16 rows x full 512 cols (so LN is block-local). 256 threads,
// per-thread 2 rows x 16 cols (4 column groups of 4, interleaved by 128).
// Row scaling by 1/Z commuted to the epilogue.
// ---------------------------------------------------------------------------
__global__ __launch_bounds__(256) void attn_ln_kernel(
    const float* __restrict__ Wt, const float* __restrict__ V,
    const float* __restrict__ x, const float* __restrict__ g1,
    const float* __restrict__ b1, float* __restrict__ Y1)
{
    __shared__ float Bs[16][512];  // V k-tile; reused as t-value stash
    __shared__ float As[16][16];   // w tile [r][k]

    const int tid = threadIdx.x;
    const int row0 = blockIdx.x * 16;
    const int vbase = row0 & ~(F_ - 1);   // all 16 rows share (b,d)
    const int tx = tid & 31, ty = tid >> 5;
    const int ar = tid >> 4, ak = tid & 15;

    float acc[2][16] = {};

    for (int k0 = 0; k0 < F_; k0 += 16) {
        float a_v = Wt[(row0 + ar) * F_ + (k0 + ak)];
        float4 bv[8];
#pragma unroll
        for (int it = 0; it < 8; it++) {
            int idx4 = tid + it * 256;
            int k = idx4 >> 7, c = (idx4 & 127) << 2;
            bv[it] = *(const float4*)&V[(vbase + k0 + k) * C_ + c];
        }
        __syncthreads();
        As[ar][ak] = a_v;
#pragma unroll
        for (int it = 0; it < 8; it++) {
            int idx4 = tid + it * 256;
            int k = idx4 >> 7, c = (idx4 & 127) << 2;
            *(float4*)&Bs[k][c] = bv[it];
        }
        __syncthreads();
#pragma unroll
        for (int kk = 0; kk < 16; kk++) {
            float a0 = As[(ty << 1) + 0][kk];
            float a1 = As[(ty << 1) + 1][kk];
#pragma unroll
            for (int cg = 0; cg < 4; cg++) {
                float4 b4 = *(const float4*)&Bs[kk][cg * 128 + (tx << 2)];
                float br[4] = {b4.x, b4.y, b4.z, b4.w};
#pragma unroll
                for (int j = 0; j < 4; j++) {
                    acc[0][cg * 4 + j] += a0 * br[j];
                    acc[1][cg * 4 + j] += a1 * br[j];
                }
            }
        }
    }

    __syncthreads();
#pragma unroll
    for (int r = 0; r < 2; r++)
#pragma unroll
        for (int cg = 0; cg < 4; cg++) {
            float4 o = {acc[r][cg*4+0], acc[r][cg*4+1], acc[r][cg*4+2], acc[r][cg*4+3]};
            *(float4*)&Bs[(ty << 1) + r][cg * 128 + (tx << 2)] = o;
        }
    __syncthreads();

    const int lane = tid & 31, wp = tid >> 5;
#pragma unroll
    for (int rr = 0; rr < 2; rr++) {
        int r = (wp << 1) + rr;
        int grow = row0 + r;
        float z = 0.f;
#pragma unroll
        for (int j = 0; j < 8; j++) z += Wt[grow * F_ + j * 32 + lane];
#pragma unroll
        for (int off = 16; off; off >>= 1) z += __shfl_xor_sync(0xffffffffu, z, off);
        float invz = 1.0f / z;

        float vals[16], s1 = 0.f, s2 = 0.f;
#pragma unroll
        for (int j = 0; j < 16; j++) {
            int c = j * 32 + lane;
            float v = Bs[r][c] * invz + x[grow * C_ + c];
            vals[j] = v; s1 += v; s2 += v * v;
        }
#pragma unroll
        for (int off = 16; off; off >>= 1) {
            s1 += __shfl_xor_sync(0xffffffffu, s1, off);
            s2 += __shfl_xor_sync(0xffffffffu, s2, off);
        }
        float mean = s1 * (1.f / 512.f);
        float var = s2 * (1.f / 512.f) - mean * mean;
        float rstd = rsqrtf(var + 1e-3f);
#pragma unroll
        for (int j = 0; j < 16; j++) {
            int c = j * 32 + lane;
            Y1[grow * C_ + c] = (vals[j] - mean) * rstd * g1[c] + b1[c];
        }
    }
}

// ---------------------------------------------------------------------------
// y2 = LN(y1 + relu(y1 @ wm + bm)) -> final output. Same structure as above.
// ---------------------------------------------------------------------------
__global__ __launch_bounds__(256) void mlp_ln_kernel(
    const float* __restrict__ Y1, const float* __restrict__ Wm,
    const float* __restrict__ bm, const float* __restrict__ g2,
    const float* __restrict__ b2, float* __restrict__ Out)
{
    __shared__ float Bs[16][512];
    __shared__ float As[16][16];

    const int tid = threadIdx.x;
    const int row0 = blockIdx.x * 16;
    const int tx = tid & 31, ty = tid >> 5;
    const int ar = tid >> 4, ak = tid & 15;

    float acc[2][16] = {};

    for (int k0 = 0; k0 < C_; k0 += 16) {
        float a_v = Y1[(row0 + ar) * C_ + (k0 + ak)];
        float4 bv[8];
#pragma unroll
        for (int it = 0; it < 8; it++) {
            int idx4 = tid + it * 256;
            int k = idx4 >> 7, c = (idx4 & 127) << 2;
            bv[it] = *(const float4*)&Wm[(k0 + k) * C_ + c];
        }
        __syncthreads();
        As[ar][ak] = a_v;
#pragma unroll
        for (int it = 0; it < 8; it++) {
            int idx4 = tid + it * 256;
            int k = idx4 >> 7, c = (idx4 & 127) << 2;
            *(float4*)&Bs[k][c] = bv[it];
        }
        __syncthreads();
#pragma unroll
        for (int kk = 0; kk < 16; kk++) {
            float a0 = As[(ty << 1) + 0][kk];
            float a1 = As[(ty << 1) + 1][kk];
#pragma unroll
            for (int cg = 0; cg < 4; cg++) {
                float4 b4 = *(const float4*)&Bs[kk][cg * 128 + (tx << 2)];
                float br[4] = {b4.x, b4.y, b4.z, b4.w};
#pragma unroll
                for (int j = 0; j < 4; j++) {
                    acc[0][cg * 4 + j] += a0 * br[j];
                    acc[1][cg * 4 + j] += a1 * br[j];
                }
            }
        }
    }

    __syncthreads();
#pragma unroll
    for (int r = 0; r < 2; r++)
#pragma unroll
        for (int cg = 0; cg < 4; cg++) {
            float4 o = {acc[r][cg*4+0], acc[r][cg*4+1], acc[r][cg*4+2], acc[r][cg*4+3]};
            *(float4*)&Bs[(ty << 1) + r][cg * 128 + (tx << 2)] = o;
        }
    __syncthreads();

    const int lane = tid & 31, wp = tid >> 5;
#pragma unroll
    for (int rr = 0; rr < 2; rr++) {
        int r = (wp << 1) + rr;
        int grow = row0 + r;

        float vals[16], s1 = 0.f, s2 = 0.f;
#pragma unroll
        for (int j = 0; j < 16; j++) {
            int c = j * 32 + lane;
            float mlp = fmaxf(Bs[r][c] + bm[c], 0.f);
            float v = Y1[grow * C_ + c] + mlp;
            vals[j] = v; s1 += v; s2 += v * v;
        }
#pragma unroll
        for (int off = 16; off; off >>= 1) {
            s1 += __shfl_xor_sync(0xffffffffu, s1, off);
            s2 += __shfl_xor_sync(0xffffffffu, s2, off);
        }
        float mean = s1 * (1.f / 512.f);
        float var = s2 * (1.f / 512.f) - mean * mean;
        float rstd = rsqrtf(var + 1e-3f);
#pragma unroll
        for (int j = 0; j < 16; j++) {
            int c = j * 32 + lane;
            Out[grow * C_ + c] = (vals[j] - mean) * rstd * g2[c] + b2[c];
        }
    }
}

// ---------------------------------------------------------------------------
extern "C" void kernel_launch(void* const* d_in, const int* in_sizes, int n_in,
                              void* d_out, int out_size)
{
    const float* x  = (const float*)d_in[0];
    const float* wq = (const float*)d_in[1];
    const float* bq = (const float*)d_in[2];
    const float* wk = (const float*)d_in[3];
    const float* bk = (const float*)d_in[4];
    const float* wv = (const float*)d_in[5];
    const float* bv = (const float*)d_in[6];
    const float* wm = (const float*)d_in[7];
    const float* bm = (const float*)d_in[8];
    const float* g1 = (const float*)d_in[9];
    const float* b1 = (const float*)d_in[10];
    const float* g2 = (const float*)d_in[11];
    const float* b2 = (const float*)d_in[12];
    float* out = (float*)d_out;

    float *Qp, *Kp, *Vp, *Wp, *Y1p;
    cudaGetSymbolAddress((void**)&Qp,  g_Q);
    cudaGetSymbolAddress((void**)&Kp,  g_K);
    cudaGetSymbolAddress((void**)&Vp,  g_V);
    cudaGetSymbolAddress((void**)&Wp,  g_Wt);
    cudaGetSymbolAddress((void**)&Y1p, g_Y1);

    // 1) Projections
    gemm_bias_kernel<<<dim3(NPOS / 64, 1), 256>>>(x, wq, bq, Qp, NPOS, R_, C_);
    gemm_bias_kernel<<<dim3(NPOS / 64, 1), 256>>>(x, wk, bk, Kp, NPOS, R_, C_);
    gemm_bias_kernel<<<dim3(NPOS / 64, C_ / 64), 256>>>(x, wv, bv, Vp, NPOS, C_, C_);

    // 2) Scores + g-fold (unnormalized softmax numerators)
    scores_kernel<<<dim3(F_ / 128, NB / 32, B_), 256>>>(Qp, Kp, Wp);

    // 3) attn + residual + LN
    attn_ln_kernel<<<NPOS / 16, 256>>>(Wp, Vp, x, g1, b1, Y1p);

    // 4) MLP + residual + LN -> out
    mlp_ln_kernel<<<NPOS / 16, 256>>>(Y1p, wm, bm, g2, b2, out);
}